// round 7
// baseline (speedup 1.0000x reference)
#include <cuda_runtime.h>
#include <cuda_bf16.h>
#include <cstdint>

// out = relu(h @ W1[0:64,:] + b1) @ W2[0:64,:] + b2   (edge weights hardcoded 0)
// Warp-level bf16 split-precision HMMA (mma.sync m16n8k16), fp32 accumulate.
// D = Ahi*Bhi + Ahi*Blo + Alo*Bhi. Layer-1 C-frag == layer-2 A-frag layout.
// One 16-row slab per warp. Swizzle split: bit4 of the XOR mask folds into the
// lane base (disjoint bit fields); bits 5-6 XOR the (s,jj) offset at runtime.

#define TPB   256

#define SWZ(o) ((uint32_t)(o) ^ ((((uint32_t)(o)) >> 3) & 0x70))

__device__ __forceinline__ uint32_t smem_u32(const void* p) {
    uint32_t a;
    asm("{ .reg .u64 t; cvta.to.shared.u64 t, %1; cvt.u32.u64 %0, t; }" : "=r"(a) : "l"(p));
    return a;
}

__device__ __forceinline__ void ldsm_x4_t(uint32_t& r0, uint32_t& r1, uint32_t& r2, uint32_t& r3,
                                          uint32_t addr) {
    asm volatile("ldmatrix.sync.aligned.m8n8.x4.trans.shared.b16 {%0,%1,%2,%3}, [%4];"
                 : "=r"(r0), "=r"(r1), "=r"(r2), "=r"(r3) : "r"(addr));
}

__device__ __forceinline__ void mma16816(float* c, uint32_t a0, uint32_t a1, uint32_t a2,
                                         uint32_t a3, uint32_t b0, uint32_t b1) {
    asm volatile(
        "mma.sync.aligned.m16n8k16.row.col.f32.bf16.bf16.f32 "
        "{%0,%1,%2,%3}, {%4,%5,%6,%7}, {%8,%9}, {%0,%1,%2,%3};"
        : "+f"(c[0]), "+f"(c[1]), "+f"(c[2]), "+f"(c[3])
        : "r"(a0), "r"(a1), "r"(a2), "r"(a3), "r"(b0), "r"(b1));
}

__device__ __forceinline__ void bsplit(float v, __nv_bfloat16& hi, __nv_bfloat16& lo) {
    hi = __float2bfloat16_rn(v);
    lo = __float2bfloat16_rn(v - __bfloat162float(hi));
}

// split float2 {even k, odd k} -> packed hi bf16x2 / lo bf16x2 (6 instrs).
__device__ __forceinline__ void split2(float2 v, uint32_t& hi, uint32_t& lo) {
    uint32_t hp;
    asm("cvt.rn.bf16x2.f32 %0, %1, %2;" : "=r"(hp) : "f"(v.y), "f"(v.x));  // lo half = v.x
    const float h0 = __uint_as_float(hp << 16);
    const float h1 = __uint_as_float(hp & 0xFFFF0000u);
    const float l0 = v.x - h0;
    const float l1 = v.y - h1;
    uint32_t lp;
    asm("cvt.rn.bf16x2.f32 %0, %1, %2;" : "=r"(lp) : "f"(l1), "f"(l0));
    hi = hp; lo = lp;
}

__global__ __launch_bounds__(TPB, 3)
void mlp_hmma_kernel(const float* __restrict__ h,
                     const float* __restrict__ W1,   // (128,64), rows 0..63 used
                     const float* __restrict__ b1,   // (64,)
                     const float* __restrict__ W2,   // (128,32), rows 0..63 used
                     const float* __restrict__ b2,   // (32,)
                     float* __restrict__ out,        // (N,32)
                     int N, int nSlabs)
{
    // Weights: [k][n] row-major bf16, 128B pitch, SW128-swizzled. Biases fp32.
    __shared__ __align__(1024) uint8_t sW1h[64 * 128];
    __shared__ __align__(1024) uint8_t sW1l[64 * 128];
    __shared__ __align__(1024) uint8_t sW2h[64 * 128];   // 32 cols used, padded pitch
    __shared__ __align__(1024) uint8_t sW2l[64 * 128];
    __shared__ float sb1[64];
    __shared__ float sb2[32];

    const int tid = threadIdx.x;
    const int wid = tid >> 5;
    const int lid = tid & 31;

    for (int i = tid; i < 64 * 64; i += TPB) {            // W1: i = k*64 + n
        const int k = i >> 6, n = i & 63;
        __nv_bfloat16 hi, lo; bsplit(W1[i], hi, lo);
        const uint32_t sw = SWZ(k * 128 + n * 2);
        *(__nv_bfloat16*)(sW1h + sw) = hi;
        *(__nv_bfloat16*)(sW1l + sw) = lo;
    }
    for (int i = tid; i < 64 * 32; i += TPB) {            // W2: i = k*32 + n
        const int k = i >> 5, n = i & 31;
        __nv_bfloat16 hi, lo; bsplit(W2[i], hi, lo);
        const uint32_t sw = SWZ(k * 128 + n * 2);
        *(__nv_bfloat16*)(sW2h + sw) = hi;
        *(__nv_bfloat16*)(sW2l + sw) = lo;
    }
    if (tid < 64) sb1[tid] = b1[tid];
    if (tid < 32) sb2[tid] = b2[tid];
    __syncthreads();

    const int slab = blockIdx.x * (TPB / 32) + wid;       // ONE slab per warp
    if (slab >= nSlabs) return;

    const int g = lid >> 2;        // row group 0..7
    const int t = lid & 3;         // col pair 0..3

    // per-lane ldmatrix source geometry
    const int lm = lid >> 3, lr = lid & 7;
    const int kr = ((lm & 1) << 3) + lr;    // k row within 16-row k-step (0..15)
    const int nc = (lm >> 1) << 3;          // n offset within 16-col n-group (0 or 8)

    // SWZ(2048s + 128kr + 32jj + 2nc):
    //   mask = (kr&7)<<4 (bits 4-6). u = 128kr+2nc (bits 4,7-10), v = 2048s+32jj
    //   (bits 5-6,11+) have disjoint bits, so SWZ(u+v) = (u ^ (mask&0x10)) + (v ^ (mask&0x60)).
    const uint32_t mask  = (uint32_t)((kr & 7) << 4);
    const uint32_t ubase = (uint32_t)(128 * kr + 2 * nc) ^ (mask & 0x10u);
    const uint32_t m56   = mask & 0x60u;
    const uint32_t a1h = smem_u32(sW1h) + ubase;
    const uint32_t a1l = smem_u32(sW1l) + ubase;
    const uint32_t a2hB = smem_u32(sW2h) + ubase;
    const uint32_t a2lB = smem_u32(sW2l) + ubase;

    const int row0 = slab * 16;
    int rA = row0 + g, rB = row0 + g + 8;
    const bool okA = rA < N, okB = rB < N;
    if (rA >= N) rA = N - 1;               // clamp loads; stores guarded
    if (rB >= N) rB = N - 1;

    const float2* __restrict__ pA = (const float2*)(h + (size_t)rA * 64);
    const float2* __restrict__ pB = (const float2*)(h + (size_t)rB * 64);

    // ---- bias-initialized accumulators ----
    float c1[8][4];
    #pragma unroll
    for (int j = 0; j < 8; ++j) {
        const float2 bj = *(const float2*)(sb1 + 8 * j + 2 * t);
        c1[j][0] = bj.x; c1[j][1] = bj.y; c1[j][2] = bj.x; c1[j][3] = bj.y;
    }

    // ---------------- Layer 1 ----------------
    #pragma unroll
    for (int s = 0; s < 4; ++s) {
        uint32_t ah[4], al[4];
        split2(pA[8 * s + t],     ah[0], al[0]);   // rows g,   k 16s+2t
        split2(pB[8 * s + t],     ah[1], al[1]);   // rows g+8
        split2(pA[8 * s + 4 + t], ah[2], al[2]);   // rows g,   k 16s+8+2t
        split2(pB[8 * s + 4 + t], ah[3], al[3]);

        #pragma unroll
        for (int jj = 0; jj < 4; ++jj) {           // n-groups of 16 cols
            const uint32_t off = (2048u * s + 32u * jj) ^ m56;
            uint32_t bh0, bh1, bh2, bh3, bl0, bl1, bl2, bl3;
            ldsm_x4_t(bh0, bh1, bh2, bh3, a1h + off);
            ldsm_x4_t(bl0, bl1, bl2, bl3, a1l + off);
            mma16816(c1[2 * jj],     ah[0], ah[1], ah[2], ah[3], bh0, bh1);
            mma16816(c1[2 * jj],     ah[0], ah[1], ah[2], ah[3], bl0, bl1);
            mma16816(c1[2 * jj],     al[0], al[1], al[2], al[3], bh0, bh1);
            mma16816(c1[2 * jj + 1], ah[0], ah[1], ah[2], ah[3], bh2, bh3);
            mma16816(c1[2 * jj + 1], ah[0], ah[1], ah[2], ah[3], bl2, bl3);
            mma16816(c1[2 * jj + 1], al[0], al[1], al[2], al[3], bh2, bh3);
        }
    }

    // ---- epilogue 1: relu + split; C-frag(ntile j) == A-frag(kstep j/2) ----
    uint32_t a2h[4][4], a2l[4][4];
    #pragma unroll
    for (int j = 0; j < 8; ++j) {
        const float x0 = fmaxf(c1[j][0], 0.f);
        const float y0 = fmaxf(c1[j][1], 0.f);
        const float x1 = fmaxf(c1[j][2], 0.f);
        const float y1 = fmaxf(c1[j][3], 0.f);
        const int s = j >> 1;
        const int o = (j & 1) << 1;                // even ntile -> a0,a1; odd -> a2,a3
        split2(make_float2(x0, y0), a2h[s][o],     a2l[s][o]);
        split2(make_float2(x1, y1), a2h[s][o + 1], a2l[s][o + 1]);
    }

    // ---------------- Layer 2 ----------------
    float c2[4][4];
    #pragma unroll
    for (int j = 0; j < 4; ++j) {
        const float2 bj = *(const float2*)(sb2 + 8 * j + 2 * t);
        c2[j][0] = bj.x; c2[j][1] = bj.y; c2[j][2] = bj.x; c2[j][3] = bj.y;
    }

    #pragma unroll
    for (int s = 0; s < 4; ++s) {
        #pragma unroll
        for (int jj = 0; jj < 2; ++jj) {
            const uint32_t off = (2048u * s + 32u * jj) ^ m56;
            uint32_t bh0, bh1, bh2, bh3, bl0, bl1, bl2, bl3;
            ldsm_x4_t(bh0, bh1, bh2, bh3, a2hB + off);
            ldsm_x4_t(bl0, bl1, bl2, bl3, a2lB + off);
            mma16816(c2[2 * jj],     a2h[s][0], a2h[s][1], a2h[s][2], a2h[s][3], bh0, bh1);
            mma16816(c2[2 * jj],     a2h[s][0], a2h[s][1], a2h[s][2], a2h[s][3], bl0, bl1);
            mma16816(c2[2 * jj],     a2l[s][0], a2l[s][1], a2l[s][2], a2l[s][3], bh0, bh1);
            mma16816(c2[2 * jj + 1], a2h[s][0], a2h[s][1], a2h[s][2], a2h[s][3], bh2, bh3);
            mma16816(c2[2 * jj + 1], a2h[s][0], a2h[s][1], a2h[s][2], a2h[s][3], bl2, bl3);
            mma16816(c2[2 * jj + 1], a2l[s][0], a2l[s][1], a2l[s][2], a2l[s][3], bh2, bh3);
        }
    }

    // ---- epilogue 2: store (float2, coalesced) ----
    #pragma unroll
    for (int j = 0; j < 4; ++j) {
        if (okA)
            *(float2*)(out + (size_t)(row0 + g) * 32 + 8 * j + 2 * t) =
                make_float2(c2[j][0], c2[j][1]);
        if (okB)
            *(float2*)(out + (size_t)(row0 + g + 8) * 32 + 8 * j + 2 * t) =
                make_float2(c2[j][2], c2[j][3]);
    }
}

extern "C" void kernel_launch(void* const* d_in, const int* in_sizes, int n_in,
                              void* d_out, int out_size)
{
    const float* h  = (const float*)d_in[0];
    const float* W1 = (const float*)d_in[1];
    const float* b1 = (const float*)d_in[2];
    const float* W2 = (const float*)d_in[3];
    const float* b2 = (const float*)d_in[4];
    float* out = (float*)d_out;

    const int N = in_sizes[0] / 64;              // 100000
    const int nSlabs = (N + 15) / 16;            // 6250

    const int grid = (nSlabs + (TPB / 32) - 1) / (TPB / 32);   // 782, 1 slab/warp
    mlp_hmma_kernel<<<grid, TPB>>>(h, W1, b1, W2, b2, out, N, nSlabs);
}

// round 8
// speedup vs baseline: 1.1807x; 1.1807x over previous
#include <cuda_runtime.h>
#include <cuda_bf16.h>
#include <cstdint>

// out = relu(h @ W1[0:64,:] + b1) @ W2[0:64,:] + b2   (edge weights hardcoded 0)
// Warp-level bf16 split-precision HMMA (mma.sync m16n8k16), fp32 accumulate.
// D = Ahi*Bhi + Ahi*Blo + Alo*Bhi. Layer-1 C-frag == layer-2 A-frag layout.
// Grid-stride, 2 slabs/warp (staging amortization). Vectorized float4 staging.
// Swizzle decomposition: SWZ(u+v) = (u ^ (m&0x10)) + (v ^ (m&0x60)), m=(kr&7)<<4.

#define TPB   256

#define SWZ(o) ((uint32_t)(o) ^ ((((uint32_t)(o)) >> 3) & 0x70))

__device__ __forceinline__ uint32_t smem_u32(const void* p) {
    uint32_t a;
    asm("{ .reg .u64 t; cvta.to.shared.u64 t, %1; cvt.u32.u64 %0, t; }" : "=r"(a) : "l"(p));
    return a;
}

__device__ __forceinline__ void ldsm_x4_t(uint32_t& r0, uint32_t& r1, uint32_t& r2, uint32_t& r3,
                                          uint32_t addr) {
    asm volatile("ldmatrix.sync.aligned.m8n8.x4.trans.shared.b16 {%0,%1,%2,%3}, [%4];"
                 : "=r"(r0), "=r"(r1), "=r"(r2), "=r"(r3) : "r"(addr));
}

__device__ __forceinline__ void mma16816(float* c, uint32_t a0, uint32_t a1, uint32_t a2,
                                         uint32_t a3, uint32_t b0, uint32_t b1) {
    asm volatile(
        "mma.sync.aligned.m16n8k16.row.col.f32.bf16.bf16.f32 "
        "{%0,%1,%2,%3}, {%4,%5,%6,%7}, {%8,%9}, {%0,%1,%2,%3};"
        : "+f"(c[0]), "+f"(c[1]), "+f"(c[2]), "+f"(c[3])
        : "r"(a0), "r"(a1), "r"(a2), "r"(a3), "r"(b0), "r"(b1));
}

// split float2 {even k, odd k} -> packed hi bf16x2 / lo bf16x2.
__device__ __forceinline__ void split2(float2 v, uint32_t& hi, uint32_t& lo) {
    uint32_t hp;
    asm("cvt.rn.bf16x2.f32 %0, %1, %2;" : "=r"(hp) : "f"(v.y), "f"(v.x));  // lo half = v.x
    const float h0 = __uint_as_float(hp << 16);
    const float h1 = __uint_as_float(hp & 0xFFFF0000u);
    const float l0 = v.x - h0;
    const float l1 = v.y - h1;
    uint32_t lp;
    asm("cvt.rn.bf16x2.f32 %0, %1, %2;" : "=r"(lp) : "f"(l1), "f"(l0));
    hi = hp; lo = lp;
}
// split float4 -> two hi bf16x2 + two lo bf16x2
__device__ __forceinline__ void split4(float4 v, uint32_t& h0, uint32_t& h1,
                                       uint32_t& l0, uint32_t& l1) {
    split2(make_float2(v.x, v.y), h0, l0);
    split2(make_float2(v.z, v.w), h1, l1);
}

__global__ __launch_bounds__(TPB, 3)
void mlp_hmma_kernel(const float* __restrict__ h,
                     const float* __restrict__ W1,   // (128,64), rows 0..63 used
                     const float* __restrict__ b1,   // (64,)
                     const float* __restrict__ W2,   // (128,32), rows 0..63 used
                     const float* __restrict__ b2,   // (32,)
                     float* __restrict__ out,        // (N,32)
                     int N, int nSlabs)
{
    // Weights: [k][n] row-major bf16, 128B pitch, SW128-swizzled. Biases fp32.
    __shared__ __align__(1024) uint8_t sW1h[64 * 128];
    __shared__ __align__(1024) uint8_t sW1l[64 * 128];
    __shared__ __align__(1024) uint8_t sW2h[64 * 128];   // 32 cols used, padded pitch
    __shared__ __align__(1024) uint8_t sW2l[64 * 128];
    __shared__ float sb1[64];
    __shared__ float sb2[32];

    const int tid = threadIdx.x;
    const int wid = tid >> 5;
    const int lid = tid & 31;

    // ---- vectorized weight staging: float4 loads, uint2 swizzled stores ----
    // 4-float span (n4..n4+3) = 8 bytes, 8B-aligned -> stays inside one 16B
    // swizzle atom, so a single SWZ of the base covers the whole uint2.
    {
        const float4* __restrict__ W1v = (const float4*)W1;   // 1024 float4
        #pragma unroll
        for (int j = 0; j < 4; ++j) {
            const int idx = tid + j * TPB;
            const int k = idx >> 4, n4 = (idx & 15) << 2;
            uint32_t h0, h1, l0, l1; split4(W1v[idx], h0, h1, l0, l1);
            const uint32_t sw = SWZ(k * 128 + n4 * 2);
            *(uint2*)(sW1h + sw) = make_uint2(h0, h1);
            *(uint2*)(sW1l + sw) = make_uint2(l0, l1);
        }
        const float4* __restrict__ W2v = (const float4*)W2;   // 512 float4
        #pragma unroll
        for (int j = 0; j < 2; ++j) {
            const int idx = tid + j * TPB;
            const int k = idx >> 3, n4 = (idx & 7) << 2;
            uint32_t h0, h1, l0, l1; split4(W2v[idx], h0, h1, l0, l1);
            const uint32_t sw = SWZ(k * 128 + n4 * 2);
            *(uint2*)(sW2h + sw) = make_uint2(h0, h1);
            *(uint2*)(sW2l + sw) = make_uint2(l0, l1);
        }
    }
    if (tid < 64) sb1[tid] = b1[tid];
    if (tid < 32) sb2[tid] = b2[tid];
    __syncthreads();

    const int g = lid >> 2;        // row group 0..7
    const int t = lid & 3;         // col pair 0..3

    // per-lane ldmatrix source geometry
    const int lm = lid >> 3, lr = lid & 7;
    const int kr = ((lm & 1) << 3) + lr;    // k row within 16-row k-step (0..15)
    const int nc = (lm >> 1) << 3;          // n offset within 16-col n-group (0 or 8)

    // SWZ(2048s + 128kr + 32jj + 2nc) = (u ^ (m&0x10)) + ((2048s+32jj) ^ (m&0x60))
    const uint32_t mask  = (uint32_t)((kr & 7) << 4);
    const uint32_t ubase = (uint32_t)(128 * kr + 2 * nc) ^ (mask & 0x10u);
    const uint32_t m56   = mask & 0x60u;
    const uint32_t a1h = smem_u32(sW1h) + ubase;
    const uint32_t a1l = smem_u32(sW1l) + ubase;
    const uint32_t a2hB = smem_u32(sW2h) + ubase;
    const uint32_t a2lB = smem_u32(sW2l) + ubase;

    const int warpsTotal = gridDim.x * (TPB / 32);
    for (int slab = blockIdx.x * (TPB / 32) + wid; slab < nSlabs; slab += warpsTotal) {
        const int row0 = slab * 16;
        int rA = row0 + g, rB = row0 + g + 8;
        const bool okA = rA < N, okB = rB < N;
        if (rA >= N) rA = N - 1;               // clamp loads; stores guarded
        if (rB >= N) rB = N - 1;

        const float2* __restrict__ pA = (const float2*)(h + (size_t)rA * 64);
        const float2* __restrict__ pB = (const float2*)(h + (size_t)rB * 64);

        // ---- bias-initialized accumulators ----
        float c1[8][4];
        #pragma unroll
        for (int j = 0; j < 8; ++j) {
            const float2 bj = *(const float2*)(sb1 + 8 * j + 2 * t);
            c1[j][0] = bj.x; c1[j][1] = bj.y; c1[j][2] = bj.x; c1[j][3] = bj.y;
        }

        // ---------------- Layer 1 ----------------
        #pragma unroll
        for (int s = 0; s < 4; ++s) {
            uint32_t ah[4], al[4];
            split2(pA[8 * s + t],     ah[0], al[0]);   // rows g,   k 16s+2t
            split2(pB[8 * s + t],     ah[1], al[1]);   // rows g+8
            split2(pA[8 * s + 4 + t], ah[2], al[2]);   // rows g,   k 16s+8+2t
            split2(pB[8 * s + 4 + t], ah[3], al[3]);

            #pragma unroll
            for (int jj = 0; jj < 4; ++jj) {           // n-groups of 16 cols
                const uint32_t off = (2048u * s + 32u * jj) ^ m56;
                uint32_t bh0, bh1, bh2, bh3, bl0, bl1, bl2, bl3;
                ldsm_x4_t(bh0, bh1, bh2, bh3, a1h + off);
                ldsm_x4_t(bl0, bl1, bl2, bl3, a1l + off);
                mma16816(c1[2 * jj],     ah[0], ah[1], ah[2], ah[3], bh0, bh1);
                mma16816(c1[2 * jj],     ah[0], ah[1], ah[2], ah[3], bl0, bl1);
                mma16816(c1[2 * jj],     al[0], al[1], al[2], al[3], bh0, bh1);
                mma16816(c1[2 * jj + 1], ah[0], ah[1], ah[2], ah[3], bh2, bh3);
                mma16816(c1[2 * jj + 1], ah[0], ah[1], ah[2], ah[3], bl2, bl3);
                mma16816(c1[2 * jj + 1], al[0], al[1], al[2], al[3], bh2, bh3);
            }
        }

        // ---- epilogue 1: relu + split; C-frag(ntile j) == A-frag(kstep j/2) ----
        uint32_t a2h[4][4], a2l[4][4];
        #pragma unroll
        for (int j = 0; j < 8; ++j) {
            const float x0 = fmaxf(c1[j][0], 0.f);
            const float y0 = fmaxf(c1[j][1], 0.f);
            const float x1 = fmaxf(c1[j][2], 0.f);
            const float y1 = fmaxf(c1[j][3], 0.f);
            const int s = j >> 1;
            const int o = (j & 1) << 1;                // even ntile -> a0,a1; odd -> a2,a3
            split2(make_float2(x0, y0), a2h[s][o],     a2l[s][o]);
            split2(make_float2(x1, y1), a2h[s][o + 1], a2l[s][o + 1]);
        }

        // ---------------- Layer 2 ----------------
        float c2[4][4];
        #pragma unroll
        for (int j = 0; j < 4; ++j) {
            const float2 bj = *(const float2*)(sb2 + 8 * j + 2 * t);
            c2[j][0] = bj.x; c2[j][1] = bj.y; c2[j][2] = bj.x; c2[j][3] = bj.y;
        }

        #pragma unroll
        for (int s = 0; s < 4; ++s) {
            #pragma unroll
            for (int jj = 0; jj < 2; ++jj) {
                const uint32_t off = (2048u * s + 32u * jj) ^ m56;
                uint32_t bh0, bh1, bh2, bh3, bl0, bl1, bl2, bl3;
                ldsm_x4_t(bh0, bh1, bh2, bh3, a2hB + off);
                ldsm_x4_t(bl0, bl1, bl2, bl3, a2lB + off);
                mma16816(c2[2 * jj],     a2h[s][0], a2h[s][1], a2h[s][2], a2h[s][3], bh0, bh1);
                mma16816(c2[2 * jj],     a2h[s][0], a2h[s][1], a2h[s][2], a2h[s][3], bl0, bl1);
                mma16816(c2[2 * jj],     a2l[s][0], a2l[s][1], a2l[s][2], a2l[s][3], bh0, bh1);
                mma16816(c2[2 * jj + 1], a2h[s][0], a2h[s][1], a2h[s][2], a2h[s][3], bh2, bh3);
                mma16816(c2[2 * jj + 1], a2h[s][0], a2h[s][1], a2h[s][2], a2h[s][3], bl2, bl3);
                mma16816(c2[2 * jj + 1], a2l[s][0], a2l[s][1], a2l[s][2], a2l[s][3], bh2, bh3);
            }
        }

        // ---- epilogue 2: store (float2, coalesced) ----
        #pragma unroll
        for (int j = 0; j < 4; ++j) {
            if (okA)
                *(float2*)(out + (size_t)(row0 + g) * 32 + 8 * j + 2 * t) =
                    make_float2(c2[j][0], c2[j][1]);
            if (okB)
                *(float2*)(out + (size_t)(row0 + g + 8) * 32 + 8 * j + 2 * t) =
                    make_float2(c2[j][2], c2[j][3]);
        }
    }
}

extern "C" void kernel_launch(void* const* d_in, const int* in_sizes, int n_in,
                              void* d_out, int out_size)
{
    const float* h  = (const float*)d_in[0];
    const float* W1 = (const float*)d_in[1];
    const float* b1 = (const float*)d_in[2];
    const float* W2 = (const float*)d_in[3];
    const float* b2 = (const float*)d_in[4];
    float* out = (float*)d_out;

    const int N = in_sizes[0] / 64;              // 100000
    const int nSlabs = (N + 15) / 16;            // 6250

    // 2 slabs per warp, balanced (391 blocks at N=100000).
    int grid = (nSlabs + 2 * (TPB / 32) - 1) / (2 * (TPB / 32));
    if (grid < 1) grid = 1;

    mlp_hmma_kernel<<<grid, TPB>>>(h, W1, b1, W2, b2, out, N, nSlabs);
}

// round 9
// speedup vs baseline: 1.4877x; 1.2600x over previous
#include <cuda_runtime.h>
#include <cuda_bf16.h>
#include <cstdint>

// out = relu(h @ W1[0:64,:] + b1) @ W2[0:64,:] + b2   (edge weights hardcoded 0)
// Warp-level bf16 split-precision HMMA (mma.sync m16n8k16), fp32 accumulate.
// D = Ahi*Bhi + Ahi*Blo + Alo*Bhi. Layer-1 C-frag == layer-2 A-frag layout.
// DUAL-SLAB: each warp computes two 16-row slabs, sharing every B fragment
// (half the LDSMs) and interleaving the two accumulator chains (MMA ILP=2).
// Layer 2 is progressive per k-step to bound register pressure.

#define TPB   256

#define SWZ(o) ((uint32_t)(o) ^ ((((uint32_t)(o)) >> 3) & 0x70))

__device__ __forceinline__ uint32_t smem_u32(const void* p) {
    uint32_t a;
    asm("{ .reg .u64 t; cvta.to.shared.u64 t, %1; cvt.u32.u64 %0, t; }" : "=r"(a) : "l"(p));
    return a;
}

__device__ __forceinline__ void ldsm_x4_t(uint32_t& r0, uint32_t& r1, uint32_t& r2, uint32_t& r3,
                                          uint32_t addr) {
    asm volatile("ldmatrix.sync.aligned.m8n8.x4.trans.shared.b16 {%0,%1,%2,%3}, [%4];"
                 : "=r"(r0), "=r"(r1), "=r"(r2), "=r"(r3) : "r"(addr));
}

__device__ __forceinline__ void mma16816(float* c, const uint32_t* a, uint32_t b0, uint32_t b1) {
    asm volatile(
        "mma.sync.aligned.m16n8k16.row.col.f32.bf16.bf16.f32 "
        "{%0,%1,%2,%3}, {%4,%5,%6,%7}, {%8,%9}, {%0,%1,%2,%3};"
        : "+f"(c[0]), "+f"(c[1]), "+f"(c[2]), "+f"(c[3])
        : "r"(a[0]), "r"(a[1]), "r"(a[2]), "r"(a[3]), "r"(b0), "r"(b1));
}

// split float2 {even k, odd k} -> packed hi bf16x2 / lo bf16x2.
__device__ __forceinline__ void split2(float2 v, uint32_t& hi, uint32_t& lo) {
    uint32_t hp;
    asm("cvt.rn.bf16x2.f32 %0, %1, %2;" : "=r"(hp) : "f"(v.y), "f"(v.x));  // lo half = v.x
    const float h0 = __uint_as_float(hp << 16);
    const float h1 = __uint_as_float(hp & 0xFFFF0000u);
    const float l0 = v.x - h0;
    const float l1 = v.y - h1;
    uint32_t lp;
    asm("cvt.rn.bf16x2.f32 %0, %1, %2;" : "=r"(lp) : "f"(l1), "f"(l0));
    hi = hp; lo = lp;
}
__device__ __forceinline__ void split4(float4 v, uint32_t& h0, uint32_t& h1,
                                       uint32_t& l0, uint32_t& l1) {
    split2(make_float2(v.x, v.y), h0, l0);
    split2(make_float2(v.z, v.w), h1, l1);
}

__global__ __launch_bounds__(TPB, 2)
void mlp_hmma_kernel(const float* __restrict__ h,
                     const float* __restrict__ W1,   // (128,64), rows 0..63 used
                     const float* __restrict__ b1,   // (64,)
                     const float* __restrict__ W2,   // (128,32), rows 0..63 used
                     const float* __restrict__ b2,   // (32,)
                     float* __restrict__ out,        // (N,32)
                     int N)
{
    // Weights: [k][n] row-major bf16, 128B pitch, SW128-swizzled. Biases fp32.
    __shared__ __align__(1024) uint8_t sW1h[64 * 128];
    __shared__ __align__(1024) uint8_t sW1l[64 * 128];
    __shared__ __align__(1024) uint8_t sW2h[64 * 128];   // 32 cols used, padded pitch
    __shared__ __align__(1024) uint8_t sW2l[64 * 128];
    __shared__ float sb1[64];
    __shared__ float sb2[32];

    const int tid = threadIdx.x;
    const int wid = tid >> 5;
    const int lid = tid & 31;

    // ---- vectorized weight staging: float4 loads, uint2 swizzled stores ----
    {
        const float4* __restrict__ W1v = (const float4*)W1;   // 1024 float4
        #pragma unroll
        for (int j = 0; j < 4; ++j) {
            const int idx = tid + j * TPB;
            const int k = idx >> 4, n4 = (idx & 15) << 2;
            uint32_t h0, h1, l0, l1; split4(W1v[idx], h0, h1, l0, l1);
            const uint32_t sw = SWZ(k * 128 + n4 * 2);
            *(uint2*)(sW1h + sw) = make_uint2(h0, h1);
            *(uint2*)(sW1l + sw) = make_uint2(l0, l1);
        }
        const float4* __restrict__ W2v = (const float4*)W2;   // 512 float4
        #pragma unroll
        for (int j = 0; j < 2; ++j) {
            const int idx = tid + j * TPB;
            const int k = idx >> 3, n4 = (idx & 7) << 2;
            uint32_t h0, h1, l0, l1; split4(W2v[idx], h0, h1, l0, l1);
            const uint32_t sw = SWZ(k * 128 + n4 * 2);
            *(uint2*)(sW2h + sw) = make_uint2(h0, h1);
            *(uint2*)(sW2l + sw) = make_uint2(l0, l1);
        }
    }
    if (tid < 64) sb1[tid] = b1[tid];
    if (tid < 32) sb2[tid] = b2[tid];
    __syncthreads();

    const int pair = blockIdx.x * (TPB / 32) + wid;       // 32 rows per warp
    const int row0 = pair * 32;
    if (row0 >= N) return;

    const int g = lid >> 2;        // row group 0..7
    const int t = lid & 3;         // col pair 0..3

    // per-lane ldmatrix source geometry
    const int lm = lid >> 3, lr = lid & 7;
    const int kr = ((lm & 1) << 3) + lr;    // k row within 16-row k-step (0..15)
    const int nc = (lm >> 1) << 3;          // n offset within 16-col n-group (0 or 8)

    // SWZ(2048s + 128kr + 32jj + 2nc) = (u ^ (m&0x10)) + ((2048s+32jj) ^ (m&0x60))
    const uint32_t mask  = (uint32_t)((kr & 7) << 4);
    const uint32_t ubase = (uint32_t)(128 * kr + 2 * nc) ^ (mask & 0x10u);
    const uint32_t m56   = mask & 0x60u;
    const uint32_t a1h = smem_u32(sW1h) + ubase;
    const uint32_t a1l = smem_u32(sW1l) + ubase;
    const uint32_t a2hB = smem_u32(sW2h) + ubase;
    const uint32_t a2lB = smem_u32(sW2l) + ubase;

    // rows: slab u covers row0+16u .. row0+16u+15; fragment rows g / g+8
    int r0 = row0 + g,      r1 = row0 + g + 8;
    int r2 = row0 + 16 + g, r3 = row0 + 24 + g;
    const bool ok0 = r0 < N, ok1 = r1 < N, ok2 = r2 < N, ok3 = r3 < N;
    if (r0 >= N) r0 = N - 1;
    if (r1 >= N) r1 = N - 1;
    if (r2 >= N) r2 = N - 1;
    if (r3 >= N) r3 = N - 1;
    const float2* __restrict__ p0 = (const float2*)(h + (size_t)r0 * 64);
    const float2* __restrict__ p1 = (const float2*)(h + (size_t)r1 * 64);
    const float2* __restrict__ p2 = (const float2*)(h + (size_t)r2 * 64);
    const float2* __restrict__ p3 = (const float2*)(h + (size_t)r3 * 64);

    // ---- layer-1 accumulators (bias-initialized), both slabs ----
    float c1[2][8][4];
    #pragma unroll
    for (int j = 0; j < 8; ++j) {
        const float2 bj = *(const float2*)(sb1 + 8 * j + 2 * t);
        #pragma unroll
        for (int u = 0; u < 2; ++u) {
            c1[u][j][0] = bj.x; c1[u][j][1] = bj.y;
            c1[u][j][2] = bj.x; c1[u][j][3] = bj.y;
        }
    }

    // ---------------- Layer 1 (B fragments shared by both slabs) ----------------
    #pragma unroll
    for (int s = 0; s < 4; ++s) {
        uint32_t ah[2][4], al[2][4];
        split2(p0[8 * s + t],     ah[0][0], al[0][0]);
        split2(p1[8 * s + t],     ah[0][1], al[0][1]);
        split2(p0[8 * s + 4 + t], ah[0][2], al[0][2]);
        split2(p1[8 * s + 4 + t], ah[0][3], al[0][3]);
        split2(p2[8 * s + t],     ah[1][0], al[1][0]);
        split2(p3[8 * s + t],     ah[1][1], al[1][1]);
        split2(p2[8 * s + 4 + t], ah[1][2], al[1][2]);
        split2(p3[8 * s + 4 + t], ah[1][3], al[1][3]);

        #pragma unroll
        for (int jj = 0; jj < 4; ++jj) {
            const uint32_t off = (2048u * s + 32u * jj) ^ m56;
            uint32_t bh0, bh1, bh2, bh3, bl0, bl1, bl2, bl3;
            ldsm_x4_t(bh0, bh1, bh2, bh3, a1h + off);
            ldsm_x4_t(bl0, bl1, bl2, bl3, a1l + off);
            // slab-interleaved: every same-acc chain has an independent twin
            mma16816(c1[0][2 * jj],     ah[0], bh0, bh1);
            mma16816(c1[1][2 * jj],     ah[1], bh0, bh1);
            mma16816(c1[0][2 * jj + 1], ah[0], bh2, bh3);
            mma16816(c1[1][2 * jj + 1], ah[1], bh2, bh3);
            mma16816(c1[0][2 * jj],     ah[0], bl0, bl1);
            mma16816(c1[1][2 * jj],     ah[1], bl0, bl1);
            mma16816(c1[0][2 * jj + 1], ah[0], bl2, bl3);
            mma16816(c1[1][2 * jj + 1], ah[1], bl2, bl3);
            mma16816(c1[0][2 * jj],     al[0], bh0, bh1);
            mma16816(c1[1][2 * jj],     al[1], bh0, bh1);
            mma16816(c1[0][2 * jj + 1], al[0], bh2, bh3);
            mma16816(c1[1][2 * jj + 1], al[1], bh2, bh3);
        }
    }

    // ---------------- Layer 2: progressive per k-step ----------------
    float c2[2][4][4];
    #pragma unroll
    for (int j = 0; j < 4; ++j) {
        const float2 bj = *(const float2*)(sb2 + 8 * j + 2 * t);
        #pragma unroll
        for (int u = 0; u < 2; ++u) {
            c2[u][j][0] = bj.x; c2[u][j][1] = bj.y;
            c2[u][j][2] = bj.x; c2[u][j][3] = bj.y;
        }
    }

    #pragma unroll
    for (int s = 0; s < 4; ++s) {
        // convert c1 ntiles {2s, 2s+1} of both slabs -> A-frags for k-step s
        uint32_t a2h[2][4], a2l[2][4];
        #pragma unroll
        for (int u = 0; u < 2; ++u) {
            #pragma unroll
            for (int jl = 0; jl < 2; ++jl) {
                const int j = 2 * s + jl;
                const int o = jl << 1;              // even ntile -> a0,a1; odd -> a2,a3
                const float x0 = fmaxf(c1[u][j][0], 0.f);
                const float y0 = fmaxf(c1[u][j][1], 0.f);
                const float x1 = fmaxf(c1[u][j][2], 0.f);
                const float y1 = fmaxf(c1[u][j][3], 0.f);
                split2(make_float2(x0, y0), a2h[u][o],     a2l[u][o]);
                split2(make_float2(x1, y1), a2h[u][o + 1], a2l[u][o + 1]);
            }
        }

        #pragma unroll
        for (int jj = 0; jj < 2; ++jj) {
            const uint32_t off = (2048u * s + 32u * jj) ^ m56;
            uint32_t bh0, bh1, bh2, bh3, bl0, bl1, bl2, bl3;
            ldsm_x4_t(bh0, bh1, bh2, bh3, a2hB + off);
            ldsm_x4_t(bl0, bl1, bl2, bl3, a2lB + off);
            mma16816(c2[0][2 * jj],     a2h[0], bh0, bh1);
            mma16816(c2[1][2 * jj],     a2h[1], bh0, bh1);
            mma16816(c2[0][2 * jj + 1], a2h[0], bh2, bh3);
            mma16816(c2[1][2 * jj + 1], a2h[1], bh2, bh3);
            mma16816(c2[0][2 * jj],     a2h[0], bl0, bl1);
            mma16816(c2[1][2 * jj],     a2h[1], bl0, bl1);
            mma16816(c2[0][2 * jj + 1], a2h[0], bl2, bl3);
            mma16816(c2[1][2 * jj + 1], a2h[1], bl2, bl3);
            mma16816(c2[0][2 * jj],     a2l[0], bh0, bh1);
            mma16816(c2[1][2 * jj],     a2l[1], bh0, bh1);
            mma16816(c2[0][2 * jj + 1], a2l[0], bh2, bh3);
            mma16816(c2[1][2 * jj + 1], a2l[1], bh2, bh3);
        }
    }

    // ---- epilogue: store (float2, coalesced) ----
    #pragma unroll
    for (int j = 0; j < 4; ++j) {
        if (ok0)
            *(float2*)(out + (size_t)(row0 + g) * 32 + 8 * j + 2 * t) =
                make_float2(c2[0][j][0], c2[0][j][1]);
        if (ok1)
            *(float2*)(out + (size_t)(row0 + g + 8) * 32 + 8 * j + 2 * t) =
                make_float2(c2[0][j][2], c2[0][j][3]);
        if (ok2)
            *(float2*)(out + (size_t)(row0 + 16 + g) * 32 + 8 * j + 2 * t) =
                make_float2(c2[1][j][0], c2[1][j][1]);
        if (ok3)
            *(float2*)(out + (size_t)(row0 + 24 + g) * 32 + 8 * j + 2 * t) =
                make_float2(c2[1][j][2], c2[1][j][3]);
    }
}

extern "C" void kernel_launch(void* const* d_in, const int* in_sizes, int n_in,
                              void* d_out, int out_size)
{
    const float* h  = (const float*)d_in[0];
    const float* W1 = (const float*)d_in[1];
    const float* b1 = (const float*)d_in[2];
    const float* W2 = (const float*)d_in[3];
    const float* b2 = (const float*)d_in[4];
    float* out = (float*)d_out;

    const int N = in_sizes[0] / 64;              // 100000
    const int nPairs = (N + 31) / 32;            // 3125 (32 rows per warp)
    const int grid = (nPairs + (TPB / 32) - 1) / (TPB / 32);   // 391

    mlp_hmma_kernel<<<grid, TPB>>>(h, W1, b1, W2, b2, out, N);
}